// round 8
// baseline (speedup 1.0000x reference)
#include <cuda_runtime.h>
#include <cuda_bf16.h>

// Problem constants
#define D      1024
#define DV     (D / 4)      // 256 float4 lanes (= blockDim)
#define L      16384
#define LF     32768
#define TS     32           // chunk length (rows per block)
#define NCH    (L / TS)     // 512 chunks
#define EPSV   1e-4f
#define LOOKW  8            // lookback window

// Scratch (__device__ globals; no dynamic allocation allowed)
__device__ float4 g_agg4[NCH * DV];   // chunk-local aggregate B_c
__device__ float4 g_pref4[NCH * DV];  // inclusive prefix after chunk c
__device__ float  g_aggA[NCH];        // chunk decay product A_c
__device__ int    g_flag[NCH];        // 0=invalid 1=aggregate 2=prefix
__device__ int    g_pos[L + 1];       // boundary positions + sentinel

// ---------------------------------------------------------------------------
// acquire/release helpers
// ---------------------------------------------------------------------------
__device__ __forceinline__ int ld_acq(const int* p) {
    int v;
    asm volatile("ld.acquire.gpu.global.b32 %0, [%1];" : "=r"(v) : "l"(p) : "memory");
    return v;
}
__device__ __forceinline__ void st_rel(int* p, int v) {
    asm volatile("st.release.gpu.global.b32 [%0], %1;" :: "l"(p), "r"(v) : "memory");
}

// ---------------------------------------------------------------------------
// K0: prep. Zero lookback flags + scan of b -> pos[].
// One block, 1024 threads, 32 b-elements each.
// ---------------------------------------------------------------------------
__global__ void k_prep(const int* __restrict__ b) {
    __shared__ int warp_tot[32];
    const int tid  = threadIdx.x;
    const int lane = tid & 31;
    const int wid  = tid >> 5;
    const int base = tid * 32;

    if (tid < NCH) g_flag[tid] = 0;

    int loc[32];
    const int4* b4 = (const int4*)(b + base);
    #pragma unroll
    for (int i = 0; i < 8; i++) {
        int4 v = b4[i];
        loc[i * 4 + 0] = v.x; loc[i * 4 + 1] = v.y;
        loc[i * 4 + 2] = v.z; loc[i * 4 + 3] = v.w;
    }
    int s = 0;
    #pragma unroll
    for (int i = 0; i < 32; i++) s += loc[i];

    int incl = s;
    #pragma unroll
    for (int off = 1; off < 32; off <<= 1) {
        int v = __shfl_up_sync(0xffffffffu, incl, off);
        if (lane >= off) incl += v;
    }
    if (lane == 31) warp_tot[wid] = incl;
    __syncthreads();
    if (wid == 0) {
        int w = warp_tot[lane];
        int wi = w;
        #pragma unroll
        for (int off = 1; off < 32; off <<= 1) {
            int v = __shfl_up_sync(0xffffffffu, wi, off);
            if (lane >= off) wi += v;
        }
        warp_tot[lane] = wi - w;
    }
    __syncthreads();
    int run = warp_tot[wid] + (incl - s);
    #pragma unroll
    for (int i = 0; i < 32; i++) {
        if (loc[i]) { g_pos[run] = base + i; run++; }
    }
    if (tid == 0) g_pos[L] = LF;
}

// ---------------------------------------------------------------------------
// K1: fused single-pass scan + scatter with decoupled lookback.
// One block per 32-step chunk. No smem staging: pass 2 re-reads x and hits
// L1/L2 (the chunk was just loaded by pass 1 in the same block).
// ---------------------------------------------------------------------------
__global__ __launch_bounds__(DV) void k_fused(
    const float* __restrict__ x, const float* __restrict__ p,
    float* __restrict__ out) {
    __shared__ float sa[TS];
    __shared__ float sb[TS];
    __shared__ int   spos[TS + 1];
    __shared__ float sA;   // chunk decay product

    const int c   = blockIdx.x;
    const int tid = threadIdx.x;

    if (tid < TS) {
        float pv = __ldg(p + c * TS + tid);
        pv = fminf(fmaxf(pv, EPSV), 1.0f - EPSV);
        sa[tid] = 1.0f - pv;
        sb[tid] = pv;
    }
    if (tid <= TS) spos[tid] = g_pos[c * TS + tid];
    __syncthreads();
    if (tid == 0) {
        float A = 1.0f;
        #pragma unroll
        for (int t = 0; t < TS; t++) A *= sa[t];
        sA = A;
    }

    // ---- pass 1: load x (default caching -> stays in L1/L2 for pass 2),
    //      compute local aggregate ----
    const float4* xr = (const float4*)x + (size_t)c * TS * DV + tid;
    float4 z = make_float4(0.f, 0.f, 0.f, 0.f);
    #pragma unroll
    for (int tb = 0; tb < TS; tb += 8) {
        float4 v[8];
        #pragma unroll
        for (int i = 0; i < 8; i++) v[i] = xr[(size_t)(tb + i) * DV];
        #pragma unroll
        for (int i = 0; i < 8; i++) {
            float a = sa[tb + i], pb = sb[tb + i];
            z.x = a * z.x + pb * v[i].x;
            z.y = a * z.y + pb * v[i].y;
            z.z = a * z.z + pb * v[i].z;
            z.w = a * z.w + pb * v[i].w;
        }
    }
    __syncthreads();   // sA visible

    // ---- publish aggregate (blocks c>0) ----
    if (c > 0) {
        g_agg4[(size_t)c * DV + tid] = z;
        if (tid == 0) g_aggA[c] = sA;
        __syncthreads();
        if (tid == 0) { __threadfence(); st_rel(&g_flag[c], 1); }
    }

    // ---- decoupled lookback: carry = exclusive prefix entering chunk c ----
    float4 carry = make_float4(0.f, 0.f, 0.f, 0.f);
    if (c > 0) {
        float mult = 1.f;
        int idx = c - 1;
        bool done = false;
        while (!done) {
            const int W = (idx + 1 < LOOKW) ? idx + 1 : LOOKW;
            int f[LOOKW];
            #pragma unroll
            for (int k = 0; k < LOOKW; k++)
                f[k] = (k < W) ? ld_acq(&g_flag[idx - k]) : 2;
            for (int k = 0; k < W; k++)
                while (f[k] == 0) f[k] = ld_acq(&g_flag[idx - k]);
            // prefetch state vectors for the whole window (independent loads)
            float4 av[LOOKW];
            float  aA[LOOKW];
            #pragma unroll
            for (int k = 0; k < LOOKW; k++) {
                if (k < W) {
                    const float4* src = (f[k] == 2) ? g_pref4 : g_agg4;
                    av[k] = src[(size_t)(idx - k) * DV + tid];
                    aA[k] = g_aggA[idx - k];
                }
            }
            #pragma unroll
            for (int k = 0; k < LOOKW; k++) {
                if (k >= W) break;
                carry.x += mult * av[k].x;
                carry.y += mult * av[k].y;
                carry.z += mult * av[k].z;
                carry.w += mult * av[k].w;
                if (f[k] == 2 || idx - k == 0) { done = true; break; }
                mult *= aA[k];
            }
            idx -= LOOKW;
        }
    }

    // ---- publish inclusive prefix: pref_c = B_c + A_c * carry ----
    {
        float A = sA;
        float4 pf;
        pf.x = z.x + A * carry.x;
        pf.y = z.y + A * carry.y;
        pf.z = z.z + A * carry.z;
        pf.w = z.w + A * carry.w;
        g_pref4[(size_t)c * DV + tid] = pf;
    }
    __syncthreads();
    if (tid == 0) { __threadfence(); st_rel(&g_flag[c], 2); }

    // ---- pass 2: re-scan (x re-read hits L1/L2), scatter to out ----
    float4* out4 = (float4*)out;
    float4 z2 = carry;
    #pragma unroll
    for (int tb = 0; tb < TS; tb += 8) {
        float4 v[8];
        #pragma unroll
        for (int i = 0; i < 8; i++) v[i] = xr[(size_t)(tb + i) * DV];
        #pragma unroll
        for (int i = 0; i < 8; i++) {
            const int t = tb + i;
            float a = sa[t], pb = sb[t];
            z2.x = a * z2.x + pb * v[i].x;
            z2.y = a * z2.y + pb * v[i].y;
            z2.z = a * z2.z + pb * v[i].z;
            z2.w = a * z2.w + pb * v[i].w;
            const int ps = spos[t], pe = spos[t + 1];
            for (int r = ps; r < pe; r++)
                __stcs(out4 + (size_t)r * DV + tid, z2);
        }
    }
}

// ---------------------------------------------------------------------------
extern "C" void kernel_launch(void* const* d_in, const int* in_sizes, int n_in,
                              void* d_out, int out_size) {
    const float* x = (const float*)d_in[0];
    const float* p = (const float*)d_in[1];
    const int*   b = (const int*)d_in[2];
    float* out = (float*)d_out;

    k_prep<<<1, 1024>>>(b);
    k_fused<<<NCH, DV>>>(x, p, out);
}

// round 10
// speedup vs baseline: 1.4702x; 1.4702x over previous
#include <cuda_runtime.h>
#include <cuda_bf16.h>

// Problem constants
#define D      1024
#define DV     (D / 4)      // 256 float4 lanes (= blockDim)
#define L      16384
#define LF     32768
#define T      32           // chunk length
#define NC     (L / T)      // 512 chunks
#define NG     32           // chunk groups
#define GS     (NC / NG)    // 16 chunks per group
#define EPSV   1e-4f

// Scratch (__device__ globals; no dynamic allocation allowed)
__device__ float4 g_B4[NC * DV];     // chunk-final local state
__device__ float4 g_Zpre4[NC * DV];  // group-LOCAL prefix entering each chunk
__device__ float4 g_Bg4[NG * DV];    // group-final local state
__device__ float4 g_Zg4[NG * DV];    // state entering each group
__device__ float  g_A[NC];           // per-chunk decay product
__device__ float  g_cumA[NC];        // prod of A within group, [group_start, c)
__device__ float  g_Ag[NG];          // per-group decay product
__device__ int    g_pos[L + 1];      // boundary positions + sentinel

// ---------------------------------------------------------------------------
// K0: scan of b (LF int32) -> pos[s] = index of s-th one; pos[L] = LF
// ---------------------------------------------------------------------------
__global__ void k_scan_b(const int* __restrict__ b) {
    __shared__ int warp_tot[32];
    const int tid  = threadIdx.x;
    const int lane = tid & 31;
    const int wid  = tid >> 5;
    const int base = tid * 32;

    int loc[32];
    const int4* b4 = (const int4*)(b + base);
    #pragma unroll
    for (int i = 0; i < 8; i++) {
        int4 v = b4[i];
        loc[i * 4 + 0] = v.x; loc[i * 4 + 1] = v.y;
        loc[i * 4 + 2] = v.z; loc[i * 4 + 3] = v.w;
    }
    int s = 0;
    #pragma unroll
    for (int i = 0; i < 32; i++) s += loc[i];

    int incl = s;
    #pragma unroll
    for (int off = 1; off < 32; off <<= 1) {
        int v = __shfl_up_sync(0xffffffffu, incl, off);
        if (lane >= off) incl += v;
    }
    if (lane == 31) warp_tot[wid] = incl;
    __syncthreads();
    if (wid == 0) {
        int w = warp_tot[lane];
        int wi = w;
        #pragma unroll
        for (int off = 1; off < 32; off <<= 1) {
            int v = __shfl_up_sync(0xffffffffu, wi, off);
            if (lane >= off) wi += v;
        }
        warp_tot[lane] = wi - w;
    }
    __syncthreads();
    int run = warp_tot[wid] + (incl - s);
    #pragma unroll
    for (int i = 0; i < 32; i++) {
        if (loc[i]) { g_pos[run] = base + i; run++; }
    }
    if (tid == 0) g_pos[L] = LF;
}

// ---------------------------------------------------------------------------
// K1: per-chunk local scan, float4 per thread, 8-row load batches.
// 512 blocks. Leaves x resident in L2 for K3's re-read.
// ---------------------------------------------------------------------------
__global__ __launch_bounds__(DV) void k_chunk_local(
    const float* __restrict__ x, const float* __restrict__ p) {
    __shared__ float sa[T];
    __shared__ float sb[T];
    const int c   = blockIdx.x;
    const int tid = threadIdx.x;

    if (tid < T) {
        float pv = __ldg(p + c * T + tid);
        pv = fminf(fmaxf(pv, EPSV), 1.0f - EPSV);
        sa[tid] = 1.0f - pv;
        sb[tid] = pv;
    }
    __syncthreads();

    const float4* xr = (const float4*)x + (size_t)c * T * DV + tid;
    float4 z = make_float4(0.f, 0.f, 0.f, 0.f);

    #pragma unroll
    for (int tb = 0; tb < T; tb += 8) {
        float4 v[8];
        #pragma unroll
        for (int i = 0; i < 8; i++) v[i] = xr[(size_t)(tb + i) * DV];
        #pragma unroll
        for (int i = 0; i < 8; i++) {
            float a = sa[tb + i], pb = sb[tb + i];
            z.x = a * z.x + pb * v[i].x;
            z.y = a * z.y + pb * v[i].y;
            z.z = a * z.z + pb * v[i].z;
            z.w = a * z.w + pb * v[i].w;
        }
    }
    g_B4[(size_t)c * DV + tid] = z;

    if (tid == 0) {
        float A = 1.0f;
        #pragma unroll
        for (int t = 0; t < T; t++) A *= sa[t];
        g_A[c] = A;
    }
}

// ---------------------------------------------------------------------------
// K2a: group-local chunk prefix. One block per group of 16 chunks.
// PREFETCH all 16 chunk vectors (independent loads, one round trip), then
// scan in registers.
// ---------------------------------------------------------------------------
__global__ __launch_bounds__(DV) void k_group_local() {
    __shared__ float sA[GS];
    const int g   = blockIdx.x;
    const int tid = threadIdx.x;
    if (tid < GS) sA[tid] = g_A[g * GS + tid];
    __syncthreads();

    float4 Bv[GS];
    #pragma unroll
    for (int j = 0; j < GS; j++)
        Bv[j] = g_B4[(size_t)(g * GS + j) * DV + tid];

    float4 z = make_float4(0.f, 0.f, 0.f, 0.f);
    float  Acum = 1.0f;
    #pragma unroll
    for (int j = 0; j < GS; j++) {
        const int c = g * GS + j;
        g_Zpre4[(size_t)c * DV + tid] = z;
        if (tid == 0) g_cumA[c] = Acum;
        float a = sA[j];
        z.x = a * z.x + Bv[j].x;
        z.y = a * z.y + Bv[j].y;
        z.z = a * z.z + Bv[j].z;
        z.w = a * z.w + Bv[j].w;
        Acum *= a;
    }
    g_Bg4[(size_t)g * DV + tid] = z;
    if (tid == 0) g_Ag[g] = Acum;
}

// ---------------------------------------------------------------------------
// K2b: scan over 32 groups. One block; prefetch all 32 group vectors
// (two batches of 16 to bound register pressure), scan in registers.
// ---------------------------------------------------------------------------
__global__ __launch_bounds__(DV) void k_group_scan() {
    __shared__ float sAg[NG];
    const int tid = threadIdx.x;
    if (tid < NG) sAg[tid] = g_Ag[tid];
    __syncthreads();

    float4 z = make_float4(0.f, 0.f, 0.f, 0.f);
    #pragma unroll
    for (int half = 0; half < 2; half++) {
        float4 Bv[16];
        #pragma unroll
        for (int j = 0; j < 16; j++)
            Bv[j] = g_Bg4[(size_t)(half * 16 + j) * DV + tid];
        #pragma unroll
        for (int j = 0; j < 16; j++) {
            const int g = half * 16 + j;
            g_Zg4[(size_t)g * DV + tid] = z;
            float a = sAg[g];
            z.x = a * z.x + Bv[j].x;
            z.y = a * z.y + Bv[j].y;
            z.z = a * z.z + Bv[j].z;
            z.w = a * z.w + Bv[j].w;
        }
    }
}

// ---------------------------------------------------------------------------
// K3: re-scan with injected prefix (group-local + cumA*groupState), scatter
// each z row to output rows [pos[s], pos[s+1]).
// x re-read should hit L2 (written there by K1); out uses streaming stores
// to avoid evicting x.
// ---------------------------------------------------------------------------
__global__ __launch_bounds__(DV) void k_rescan_scatter(
    const float* __restrict__ x, const float* __restrict__ p,
    float* __restrict__ out) {
    __shared__ float sa[T];
    __shared__ float sb[T];
    __shared__ int   spos[T + 1];
    const int c   = blockIdx.x;
    const int tid = threadIdx.x;

    if (tid < T) {
        float pv = __ldg(p + c * T + tid);
        pv = fminf(fmaxf(pv, EPSV), 1.0f - EPSV);
        sa[tid] = 1.0f - pv;
        sb[tid] = pv;
    }
    if (tid <= T) spos[tid] = g_pos[c * T + tid];
    __syncthreads();

    // z_pre(c) = Zpre_local(c) + cumA(c) * Zg(group(c))
    float  ca = g_cumA[c];
    float4 zl = g_Zpre4[(size_t)c * DV + tid];
    float4 zg = g_Zg4[(size_t)(c / GS) * DV + tid];
    float4 z;
    z.x = zl.x + ca * zg.x;
    z.y = zl.y + ca * zg.y;
    z.z = zl.z + ca * zg.z;
    z.w = zl.w + ca * zg.w;

    const float4* xr   = (const float4*)x + (size_t)c * T * DV + tid;
    float4*       out4 = (float4*)out;

    #pragma unroll
    for (int tb = 0; tb < T; tb += 8) {
        float4 v[8];
        #pragma unroll
        for (int i = 0; i < 8; i++) v[i] = xr[(size_t)(tb + i) * DV];
        #pragma unroll
        for (int i = 0; i < 8; i++) {
            const int t = tb + i;
            float a = sa[t], pb = sb[t];
            z.x = a * z.x + pb * v[i].x;
            z.y = a * z.y + pb * v[i].y;
            z.z = a * z.z + pb * v[i].z;
            z.w = a * z.w + pb * v[i].w;
            const int ps = spos[t], pe = spos[t + 1];
            for (int r = ps; r < pe; r++)
                __stcs(out4 + (size_t)r * DV + tid, z);
        }
    }
}

// ---------------------------------------------------------------------------
extern "C" void kernel_launch(void* const* d_in, const int* in_sizes, int n_in,
                              void* d_out, int out_size) {
    const float* x = (const float*)d_in[0];
    const float* p = (const float*)d_in[1];
    const int*   b = (const int*)d_in[2];
    float* out = (float*)d_out;

    k_scan_b<<<1, 1024>>>(b);
    k_chunk_local<<<NC, DV>>>(x, p);
    k_group_local<<<NG, DV>>>();
    k_group_scan<<<1, DV>>>();
    k_rescan_scatter<<<NC, DV>>>(x, p, out);
}

// round 12
// speedup vs baseline: 1.5104x; 1.0274x over previous
#include <cuda_runtime.h>
#include <cuda_bf16.h>

// Problem constants
#define D      1024
#define DV     (D / 4)      // 256 float4 lanes (= blockDim)
#define L      16384
#define LF     32768
#define T      32           // chunk length
#define NC     (L / T)      // 512 chunks
#define NG     32           // chunk groups
#define GS     (NC / NG)    // 16 chunks per group
#define EPSV   1e-4f

// Scratch (__device__ globals; no dynamic allocation allowed)
__device__ float4 g_B4[NC * DV];     // chunk-final local state
__device__ float4 g_Zpre4[NC * DV];  // group-LOCAL prefix entering each chunk
__device__ float4 g_Bg4[NG * DV];    // group-final local state
__device__ float4 g_Zg4[NG * DV];    // state entering each group
__device__ float  g_A[NC];           // per-chunk decay product
__device__ float  g_cumA[NC];        // prod of A within group, [group_start, c)
__device__ float  g_Ag[NG];          // per-group decay product
__device__ int    g_pos[L + 1];      // boundary positions + sentinel

// ---------------------------------------------------------------------------
// b-scan device function: 256 threads, 128 b-elements each, two-pass
// (count then emit). Runs as the extra block of k_chunk_local.
// ---------------------------------------------------------------------------
__device__ void bscan_256(const int* __restrict__ b) {
    __shared__ int warp_tot[8];
    const int tid  = threadIdx.x;
    const int lane = tid & 31;
    const int wid  = tid >> 5;
    const int base = tid * 128;

    // pass 1: per-thread count
    const int4* b4 = (const int4*)(b + base);
    int s = 0;
    #pragma unroll
    for (int i = 0; i < 32; i++) {
        int4 v = b4[i];
        s += v.x + v.y + v.z + v.w;
    }

    // warp inclusive scan of per-thread counts
    int incl = s;
    #pragma unroll
    for (int off = 1; off < 32; off <<= 1) {
        int v = __shfl_up_sync(0xffffffffu, incl, off);
        if (lane >= off) incl += v;
    }
    if (lane == 31) warp_tot[wid] = incl;
    __syncthreads();
    if (wid == 0 && lane < 8) {
        int w = warp_tot[lane];
        int wi = w;
        #pragma unroll
        for (int off = 1; off < 8; off <<= 1) {
            int v = __shfl_up_sync(0xffu, wi, off);
            if (lane >= off) wi += v;
        }
        warp_tot[lane] = wi - w;   // exclusive warp prefix
    }
    __syncthreads();
    int run = warp_tot[wid] + (incl - s);  // exclusive prefix for this thread

    // pass 2: re-read (L2-hot) and emit positions
    #pragma unroll
    for (int i = 0; i < 32; i++) {
        int4 v = b4[i];
        int idx = base + i * 4;
        if (v.x) g_pos[run++] = idx;
        if (v.y) g_pos[run++] = idx + 1;
        if (v.z) g_pos[run++] = idx + 2;
        if (v.w) g_pos[run++] = idx + 3;
    }
    if (tid == 0) g_pos[L] = LF;
}

// ---------------------------------------------------------------------------
// K1: per-chunk local scan, float4 per thread, 8-row load batches.
// grid = NC+1: block NC runs the b-scan concurrently.
// Leaves x resident in L2 for K3's re-read.
// ---------------------------------------------------------------------------
__global__ __launch_bounds__(DV) void k_chunk_local(
    const float* __restrict__ x, const float* __restrict__ p,
    const int* __restrict__ b) {
    const int c   = blockIdx.x;
    const int tid = threadIdx.x;

    if (c == NC) { bscan_256(b); return; }

    __shared__ float sa[T];
    __shared__ float sb[T];
    if (tid < T) {
        float pv = __ldg(p + c * T + tid);
        pv = fminf(fmaxf(pv, EPSV), 1.0f - EPSV);
        sa[tid] = 1.0f - pv;
        sb[tid] = pv;
    }
    __syncthreads();

    const float4* xr = (const float4*)x + (size_t)c * T * DV + tid;
    float4 z = make_float4(0.f, 0.f, 0.f, 0.f);

    #pragma unroll
    for (int tb = 0; tb < T; tb += 8) {
        float4 v[8];
        #pragma unroll
        for (int i = 0; i < 8; i++) v[i] = xr[(size_t)(tb + i) * DV];
        #pragma unroll
        for (int i = 0; i < 8; i++) {
            float a = sa[tb + i], pb = sb[tb + i];
            z.x = a * z.x + pb * v[i].x;
            z.y = a * z.y + pb * v[i].y;
            z.z = a * z.z + pb * v[i].z;
            z.w = a * z.w + pb * v[i].w;
        }
    }
    g_B4[(size_t)c * DV + tid] = z;

    if (tid == 0) {
        float A = 1.0f;
        #pragma unroll
        for (int t = 0; t < T; t++) A *= sa[t];
        g_A[c] = A;
    }
}

// ---------------------------------------------------------------------------
// K2a: group-local chunk prefix. One block per group of 16 chunks.
// Prefetch all 16 chunk vectors (independent loads), scan in registers.
// ---------------------------------------------------------------------------
__global__ __launch_bounds__(DV) void k_group_local() {
    __shared__ float sA[GS];
    const int g   = blockIdx.x;
    const int tid = threadIdx.x;
    if (tid < GS) sA[tid] = g_A[g * GS + tid];
    __syncthreads();

    float4 Bv[GS];
    #pragma unroll
    for (int j = 0; j < GS; j++)
        Bv[j] = g_B4[(size_t)(g * GS + j) * DV + tid];

    float4 z = make_float4(0.f, 0.f, 0.f, 0.f);
    float  Acum = 1.0f;
    #pragma unroll
    for (int j = 0; j < GS; j++) {
        const int c = g * GS + j;
        g_Zpre4[(size_t)c * DV + tid] = z;
        if (tid == 0) g_cumA[c] = Acum;
        float a = sA[j];
        z.x = a * z.x + Bv[j].x;
        z.y = a * z.y + Bv[j].y;
        z.z = a * z.z + Bv[j].z;
        z.w = a * z.w + Bv[j].w;
        Acum *= a;
    }
    g_Bg4[(size_t)g * DV + tid] = z;
    if (tid == 0) g_Ag[g] = Acum;
}

// ---------------------------------------------------------------------------
// K2b: PARALLEL group prefix. Block g computes
//   Zg[g] = sum_{h<g} (prod_{h<j<g} Ag[j]) * Bg[h]
// directly: all Bg loads for a window are independent (one round trip),
// weights via a scalar recurrence iterating h downward from g-1.
// Redundant O(NG^2) total compute, trivial cost; wall time ~1 round trip.
// ---------------------------------------------------------------------------
__global__ __launch_bounds__(DV) void k_group_zg() {
    __shared__ float sAg[NG];
    const int g   = blockIdx.x;
    const int tid = threadIdx.x;
    if (tid < NG) sAg[tid] = g_Ag[tid];
    __syncthreads();

    float4 z = make_float4(0.f, 0.f, 0.f, 0.f);
    float  w = 1.0f;
    int h = g - 1;
    while (h >= 0) {
        const int n = (h + 1 < 16) ? h + 1 : 16;
        float4 Bv[16];
        for (int j = 0; j < n; j++)
            Bv[j] = g_Bg4[(size_t)(h - j) * DV + tid];
        for (int j = 0; j < n; j++) {
            z.x += w * Bv[j].x;
            z.y += w * Bv[j].y;
            z.z += w * Bv[j].z;
            z.w += w * Bv[j].w;
            w *= sAg[h - j];
        }
        h -= 16;
    }
    g_Zg4[(size_t)g * DV + tid] = z;
}

// ---------------------------------------------------------------------------
// K3: re-scan with injected prefix (group-local + cumA*groupState), scatter
// each z row to output rows [pos[s], pos[s+1]).
// x re-read hits L2 (loaded by K1); out uses streaming stores.
// ---------------------------------------------------------------------------
__global__ __launch_bounds__(DV) void k_rescan_scatter(
    const float* __restrict__ x, const float* __restrict__ p,
    float* __restrict__ out) {
    __shared__ float sa[T];
    __shared__ float sb[T];
    __shared__ int   spos[T + 1];
    const int c   = blockIdx.x;
    const int tid = threadIdx.x;

    if (tid < T) {
        float pv = __ldg(p + c * T + tid);
        pv = fminf(fmaxf(pv, EPSV), 1.0f - EPSV);
        sa[tid] = 1.0f - pv;
        sb[tid] = pv;
    }
    if (tid <= T) spos[tid] = g_pos[c * T + tid];
    __syncthreads();

    // z_pre(c) = Zpre_local(c) + cumA(c) * Zg(group(c))
    float  ca = g_cumA[c];
    float4 zl = g_Zpre4[(size_t)c * DV + tid];
    float4 zg = g_Zg4[(size_t)(c / GS) * DV + tid];
    float4 z;
    z.x = zl.x + ca * zg.x;
    z.y = zl.y + ca * zg.y;
    z.z = zl.z + ca * zg.z;
    z.w = zl.w + ca * zg.w;

    const float4* xr   = (const float4*)x + (size_t)c * T * DV + tid;
    float4*       out4 = (float4*)out;

    #pragma unroll
    for (int tb = 0; tb < T; tb += 8) {
        float4 v[8];
        #pragma unroll
        for (int i = 0; i < 8; i++) v[i] = xr[(size_t)(tb + i) * DV];
        #pragma unroll
        for (int i = 0; i < 8; i++) {
            const int t = tb + i;
            float a = sa[t], pb = sb[t];
            z.x = a * z.x + pb * v[i].x;
            z.y = a * z.y + pb * v[i].y;
            z.z = a * z.z + pb * v[i].z;
            z.w = a * z.w + pb * v[i].w;
            const int ps = spos[t], pe = spos[t + 1];
            for (int r = ps; r < pe; r++)
                __stcs(out4 + (size_t)r * DV + tid, z);
        }
    }
}

// ---------------------------------------------------------------------------
extern "C" void kernel_launch(void* const* d_in, const int* in_sizes, int n_in,
                              void* d_out, int out_size) {
    const float* x = (const float*)d_in[0];
    const float* p = (const float*)d_in[1];
    const int*   b = (const int*)d_in[2];
    float* out = (float*)d_out;

    k_chunk_local<<<NC + 1, DV>>>(x, p, b);
    k_group_local<<<NG, DV>>>();
    k_group_zg<<<NG, DV>>>();
    k_rescan_scatter<<<NC, DV>>>(x, p, out);
}

// round 13
// speedup vs baseline: 1.5147x; 1.0028x over previous
#include <cuda_runtime.h>
#include <cuda_bf16.h>

// Problem constants
#define D      1024
#define DV     (D / 4)      // 256 float4 lanes (= blockDim)
#define L      16384
#define LF     32768
#define T      32           // chunk length
#define NC     (L / T)      // 512 chunks
#define NG     32           // chunk groups
#define GS     (NC / NG)    // 16 chunks per group
#define EPSV   1e-4f

// Scratch (__device__ globals; no dynamic allocation allowed)
__device__ float4 g_B4[NC * DV];     // chunk-final local state
__device__ float4 g_Zpre4[NC * DV];  // group-LOCAL prefix entering each chunk
__device__ float4 g_Bg4[NG * DV];    // group-final local state
__device__ float4 g_Zg4[NG * DV];    // state entering each group
__device__ float  g_A[NC];           // per-chunk decay product
__device__ float  g_cumA[NC];        // prod of A within group, [group_start, c)
__device__ float  g_Ag[NG];          // per-group decay product
__device__ int    g_pos[L + 1];      // boundary positions + sentinel

// ---------------------------------------------------------------------------
// b-scan device function: 256 threads, 128 b-elements each, two-pass
// (count then emit). Runs as the extra block of k_chunk_local.
// ---------------------------------------------------------------------------
__device__ void bscan_256(const int* __restrict__ b) {
    __shared__ int warp_tot[8];
    const int tid  = threadIdx.x;
    const int lane = tid & 31;
    const int wid  = tid >> 5;
    const int base = tid * 128;

    const int4* b4 = (const int4*)(b + base);
    int s = 0;
    #pragma unroll
    for (int i = 0; i < 32; i++) {
        int4 v = b4[i];
        s += v.x + v.y + v.z + v.w;
    }

    int incl = s;
    #pragma unroll
    for (int off = 1; off < 32; off <<= 1) {
        int v = __shfl_up_sync(0xffffffffu, incl, off);
        if (lane >= off) incl += v;
    }
    if (lane == 31) warp_tot[wid] = incl;
    __syncthreads();
    if (wid == 0 && lane < 8) {
        int w = warp_tot[lane];
        int wi = w;
        #pragma unroll
        for (int off = 1; off < 8; off <<= 1) {
            int v = __shfl_up_sync(0xffu, wi, off);
            if (lane >= off) wi += v;
        }
        warp_tot[lane] = wi - w;
    }
    __syncthreads();
    int run = warp_tot[wid] + (incl - s);

    #pragma unroll
    for (int i = 0; i < 32; i++) {
        int4 v = b4[i];
        int idx = base + i * 4;
        if (v.x) g_pos[run++] = idx;
        if (v.y) g_pos[run++] = idx + 1;
        if (v.z) g_pos[run++] = idx + 2;
        if (v.w) g_pos[run++] = idx + 3;
    }
    if (tid == 0) g_pos[L] = LF;
}

// ---------------------------------------------------------------------------
// K1: per-chunk local scan, software-pipelined 8-row load batches
// (batch k+1 issued before computing batch k).
// grid = NC+1: block NC runs the b-scan concurrently.
// ---------------------------------------------------------------------------
__global__ __launch_bounds__(DV, 2) void k_chunk_local(
    const float* __restrict__ x, const float* __restrict__ p,
    const int* __restrict__ b) {
    const int c   = blockIdx.x;
    const int tid = threadIdx.x;

    if (c == NC) { bscan_256(b); return; }

    __shared__ float sa[T];
    __shared__ float sb[T];
    if (tid < T) {
        float pv = __ldg(p + c * T + tid);
        pv = fminf(fmaxf(pv, EPSV), 1.0f - EPSV);
        sa[tid] = 1.0f - pv;
        sb[tid] = pv;
    }
    __syncthreads();

    const float4* xr = (const float4*)x + (size_t)c * T * DV + tid;
    float4 z = make_float4(0.f, 0.f, 0.f, 0.f);

    float4 v[2][8];
    #pragma unroll
    for (int i = 0; i < 8; i++) v[0][i] = xr[(size_t)i * DV];

    #pragma unroll
    for (int tb = 0; tb < T; tb += 8) {
        const int cur = (tb >> 3) & 1;
        const int nxt = cur ^ 1;
        if (tb + 8 < T) {
            #pragma unroll
            for (int i = 0; i < 8; i++)
                v[nxt][i] = xr[(size_t)(tb + 8 + i) * DV];
        }
        #pragma unroll
        for (int i = 0; i < 8; i++) {
            float a = sa[tb + i], pb = sb[tb + i];
            z.x = a * z.x + pb * v[cur][i].x;
            z.y = a * z.y + pb * v[cur][i].y;
            z.z = a * z.z + pb * v[cur][i].z;
            z.w = a * z.w + pb * v[cur][i].w;
        }
    }
    g_B4[(size_t)c * DV + tid] = z;

    if (tid == 0) {
        float A = 1.0f;
        #pragma unroll
        for (int t = 0; t < T; t++) A *= sa[t];
        g_A[c] = A;
    }
}

// ---------------------------------------------------------------------------
// K2a: group-local chunk prefix. One block per group of 16 chunks.
// Prefetch all 16 chunk vectors (independent loads), scan in registers.
// ---------------------------------------------------------------------------
__global__ __launch_bounds__(DV) void k_group_local() {
    __shared__ float sA[GS];
    const int g   = blockIdx.x;
    const int tid = threadIdx.x;
    if (tid < GS) sA[tid] = g_A[g * GS + tid];
    __syncthreads();

    float4 Bv[GS];
    #pragma unroll
    for (int j = 0; j < GS; j++)
        Bv[j] = g_B4[(size_t)(g * GS + j) * DV + tid];

    float4 z = make_float4(0.f, 0.f, 0.f, 0.f);
    float  Acum = 1.0f;
    #pragma unroll
    for (int j = 0; j < GS; j++) {
        const int c = g * GS + j;
        g_Zpre4[(size_t)c * DV + tid] = z;
        if (tid == 0) g_cumA[c] = Acum;
        float a = sA[j];
        z.x = a * z.x + Bv[j].x;
        z.y = a * z.y + Bv[j].y;
        z.z = a * z.z + Bv[j].z;
        z.w = a * z.w + Bv[j].w;
        Acum *= a;
    }
    g_Bg4[(size_t)g * DV + tid] = z;
    if (tid == 0) g_Ag[g] = Acum;
}

// ---------------------------------------------------------------------------
// K2b: PARALLEL group prefix. Block g computes
//   Zg[g] = sum_{h<g} (prod_{h<j<g} Ag[j]) * Bg[h]
// with windowed independent prefetch.
// ---------------------------------------------------------------------------
__global__ __launch_bounds__(DV) void k_group_zg() {
    __shared__ float sAg[NG];
    const int g   = blockIdx.x;
    const int tid = threadIdx.x;
    if (tid < NG) sAg[tid] = g_Ag[tid];
    __syncthreads();

    float4 z = make_float4(0.f, 0.f, 0.f, 0.f);
    float  w = 1.0f;
    int h = g - 1;
    while (h >= 0) {
        const int n = (h + 1 < 16) ? h + 1 : 16;
        float4 Bv[16];
        for (int j = 0; j < n; j++)
            Bv[j] = g_Bg4[(size_t)(h - j) * DV + tid];
        for (int j = 0; j < n; j++) {
            z.x += w * Bv[j].x;
            z.y += w * Bv[j].y;
            z.z += w * Bv[j].z;
            z.w += w * Bv[j].w;
            w *= sAg[h - j];
        }
        h -= 16;
    }
    g_Zg4[(size_t)g * DV + tid] = z;
}

// ---------------------------------------------------------------------------
// K3: re-scan with injected prefix, software-pipelined loads, scatter each
// z row to output rows [pos[s], pos[s+1]) with streaming float4 stores.
// ---------------------------------------------------------------------------
__global__ __launch_bounds__(DV, 2) void k_rescan_scatter(
    const float* __restrict__ x, const float* __restrict__ p,
    float* __restrict__ out) {
    __shared__ float sa[T];
    __shared__ float sb[T];
    __shared__ int   spos[T + 1];
    const int c   = blockIdx.x;
    const int tid = threadIdx.x;

    if (tid < T) {
        float pv = __ldg(p + c * T + tid);
        pv = fminf(fmaxf(pv, EPSV), 1.0f - EPSV);
        sa[tid] = 1.0f - pv;
        sb[tid] = pv;
    }
    if (tid <= T) spos[tid] = g_pos[c * T + tid];
    __syncthreads();

    // z_pre(c) = Zpre_local(c) + cumA(c) * Zg(group(c))
    float  ca = g_cumA[c];
    float4 zl = g_Zpre4[(size_t)c * DV + tid];
    float4 zg = g_Zg4[(size_t)(c / GS) * DV + tid];
    float4 z;
    z.x = zl.x + ca * zg.x;
    z.y = zl.y + ca * zg.y;
    z.z = zl.z + ca * zg.z;
    z.w = zl.w + ca * zg.w;

    const float4* xr   = (const float4*)x + (size_t)c * T * DV + tid;
    float4*       out4 = (float4*)out;

    float4 v[2][8];
    #pragma unroll
    for (int i = 0; i < 8; i++) v[0][i] = xr[(size_t)i * DV];

    #pragma unroll
    for (int tb = 0; tb < T; tb += 8) {
        const int cur = (tb >> 3) & 1;
        const int nxt = cur ^ 1;
        if (tb + 8 < T) {
            #pragma unroll
            for (int i = 0; i < 8; i++)
                v[nxt][i] = xr[(size_t)(tb + 8 + i) * DV];
        }
        #pragma unroll
        for (int i = 0; i < 8; i++) {
            const int t = tb + i;
            float a = sa[t], pb = sb[t];
            z.x = a * z.x + pb * v[cur][i].x;
            z.y = a * z.y + pb * v[cur][i].y;
            z.z = a * z.z + pb * v[cur][i].z;
            z.w = a * z.w + pb * v[cur][i].w;
            const int ps = spos[t], pe = spos[t + 1];
            for (int r = ps; r < pe; r++)
                __stcs(out4 + (size_t)r * DV + tid, z);
        }
    }
}

// ---------------------------------------------------------------------------
extern "C" void kernel_launch(void* const* d_in, const int* in_sizes, int n_in,
                              void* d_out, int out_size) {
    const float* x = (const float*)d_in[0];
    const float* p = (const float*)d_in[1];
    const int*   b = (const int*)d_in[2];
    float* out = (float*)d_out;

    k_chunk_local<<<NC + 1, DV>>>(x, p, b);
    k_group_local<<<NG, DV>>>();
    k_group_zg<<<NG, DV>>>();
    k_rescan_scatter<<<NC, DV>>>(x, p, out);
}